// round 7
// baseline (speedup 1.0000x reference)
#include <cuda_runtime.h>

// Problem constants
#define TT 512
#define BB 64
#define HH 768
#define LHD 384
#define G4 1536
#define NLAB 12
#define NEGV (-1000.0f)
#define NBLK_LSTM 96

// ---------------- scratch (static device memory; no allocation) -------------
// X[dir][t][col][b], col = gate*384 + j   (2*512*1536*64)
__device__ float g_X[100663296];
// Hseq[dir][t][j][b]                      (2*512*384*64)
__device__ float g_Hseq[25165824];
// feats[b][t][l]
__device__ float g_feats[64 * 512 * 12];
// per-CTA step-completion flags (monotone within a call; reset per call)
__device__ volatile int g_flag[NBLK_LSTM];

__device__ __forceinline__ float sigm(float x) {
    return 1.0f / (1.0f + __expf(-x));
}

// packed f32x2 FMA (Blackwell): d = a*b + c on both lanes, full fp32 accuracy
__device__ __forceinline__ float2 ffma2(float2 a, float2 b, float2 c) {
    union U { float2 f; unsigned long long u; };
    U A, B, C, D;
    A.f = a; B.f = b; C.f = c;
    asm("fma.rn.f32x2 %0, %1, %2, %3;"
        : "=l"(D.u) : "l"(A.u), "l"(B.u), "l"(C.u));
    return D.f;
}

// ---------------- kernel A: input projection GEMM ---------------------------
// X[dir][t][col][b] = sum_k hidden[b][t][k] * w_ih[dir][col][k] + b_ih + b_hh
__global__ void __launch_bounds__(256) proj_kernel(
    const float* __restrict__ hid,
    const float* __restrict__ wf, const float* __restrict__ wb,
    const float* __restrict__ bif, const float* __restrict__ bhf,
    const float* __restrict__ bib, const float* __restrict__ bhb)
{
    __shared__ float smempool[64 * 129];   // aliases As|Bs then Cs
    float* As = smempool;                   // [16][64]
    float* Bs = smempool + 16 * 64;         // [16][128]

    int t = blockIdx.y;
    int n0 = blockIdx.x * 128;
    int dir = blockIdx.z;
    const float* w = dir ? wb : wf;

    int tid = threadIdx.x;
    int tx = tid & 15;        // col group: cols tx*8 .. tx*8+7
    int ty = tid >> 4;        // batch group: batch ty*4 .. ty*4+3

    float2 acc[4][4];
#pragma unroll
    for (int i = 0; i < 4; i++)
#pragma unroll
        for (int j = 0; j < 4; j++) acc[i][j] = make_float2(0.f, 0.f);

    int lb = tid >> 2;
    int lk = (tid & 3) * 4;
    const float* hidb = hid + (size_t)lb * TT * HH + (size_t)t * HH;
    int bc = tid >> 1;
    int bk = (tid & 1) * 8;
    const float* wrow = w + (size_t)(n0 + bc) * HH;

    for (int k0 = 0; k0 < HH; k0 += 16) {
        float4 a = *(const float4*)(hidb + k0 + lk);
        As[(lk + 0) * 64 + lb] = a.x; As[(lk + 1) * 64 + lb] = a.y;
        As[(lk + 2) * 64 + lb] = a.z; As[(lk + 3) * 64 + lb] = a.w;
        float4 b0 = *(const float4*)(wrow + k0 + bk);
        float4 b1 = *(const float4*)(wrow + k0 + bk + 4);
        Bs[(bk + 0) * 128 + bc] = b0.x; Bs[(bk + 1) * 128 + bc] = b0.y;
        Bs[(bk + 2) * 128 + bc] = b0.z; Bs[(bk + 3) * 128 + bc] = b0.w;
        Bs[(bk + 4) * 128 + bc] = b1.x; Bs[(bk + 5) * 128 + bc] = b1.y;
        Bs[(bk + 6) * 128 + bc] = b1.z; Bs[(bk + 7) * 128 + bc] = b1.w;
        __syncthreads();
#pragma unroll
        for (int k = 0; k < 16; k++) {
            float4 ra  = *(const float4*)&As[k * 64 + ty * 4];
            float4 rb0 = *(const float4*)&Bs[k * 128 + tx * 8];
            float4 rb1 = *(const float4*)&Bs[k * 128 + tx * 8 + 4];
            float2 bp0 = make_float2(rb0.x, rb0.y);
            float2 bp1 = make_float2(rb0.z, rb0.w);
            float2 bp2 = make_float2(rb1.x, rb1.y);
            float2 bp3 = make_float2(rb1.z, rb1.w);
            float2 aa;
            aa = make_float2(ra.x, ra.x);
            acc[0][0] = ffma2(aa, bp0, acc[0][0]);
            acc[0][1] = ffma2(aa, bp1, acc[0][1]);
            acc[0][2] = ffma2(aa, bp2, acc[0][2]);
            acc[0][3] = ffma2(aa, bp3, acc[0][3]);
            aa = make_float2(ra.y, ra.y);
            acc[1][0] = ffma2(aa, bp0, acc[1][0]);
            acc[1][1] = ffma2(aa, bp1, acc[1][1]);
            acc[1][2] = ffma2(aa, bp2, acc[1][2]);
            acc[1][3] = ffma2(aa, bp3, acc[1][3]);
            aa = make_float2(ra.z, ra.z);
            acc[2][0] = ffma2(aa, bp0, acc[2][0]);
            acc[2][1] = ffma2(aa, bp1, acc[2][1]);
            acc[2][2] = ffma2(aa, bp2, acc[2][2]);
            acc[2][3] = ffma2(aa, bp3, acc[2][3]);
            aa = make_float2(ra.w, ra.w);
            acc[3][0] = ffma2(aa, bp0, acc[3][0]);
            acc[3][1] = ffma2(aa, bp1, acc[3][1]);
            acc[3][2] = ffma2(aa, bp2, acc[3][2]);
            acc[3][3] = ffma2(aa, bp3, acc[3][3]);
        }
        __syncthreads();
    }

    float* Cs = smempool;
#pragma unroll
    for (int i = 0; i < 4; i++)
#pragma unroll
        for (int p = 0; p < 4; p++) {
            Cs[(ty * 4 + i) * 129 + tx * 8 + 2 * p]     = acc[i][p].x;
            Cs[(ty * 4 + i) * 129 + tx * 8 + 2 * p + 1] = acc[i][p].y;
        }
    __syncthreads();

    const float* b1 = dir ? bib : bif;
    const float* b2 = dir ? bhb : bhf;
    float* outb = g_X + (((size_t)dir * TT + t) * G4 + n0) * BB;
#pragma unroll
    for (int e = 0; e < 8; e++) {
        int idx = e * 256 + tid;
        int c = idx >> 4;
        int b4 = (idx & 15) * 4;
        float bias = b1[n0 + c] + b2[n0 + c];
        float4 v;
        v.x = Cs[(b4 + 0) * 129 + c] + bias;
        v.y = Cs[(b4 + 1) * 129 + c] + bias;
        v.z = Cs[(b4 + 2) * 129 + c] + bias;
        v.w = Cs[(b4 + 3) * 129 + c] + bias;
        *(float4*)&outb[c * 64 + b4] = v;
    }
}

// ---------------- reset flags (also shifts ncu's profiled launch slot) -------
__global__ void reset_flags_kernel() {
    if (threadIdx.x < NBLK_LSTM) g_flag[threadIdx.x] = 0;
}

// ---------------- kernel B: persistent BiLSTM recurrence ---------------------
// 96 CTAs: tile = (dir, 32 cols = 8 units x 4 gates) x 64 batch.
// Dynamic smem: Ws[384][32] (48KB) + Hs[384][64] (96KB) = 144KB, 1 CTA/SM.
// Sync: per-CTA release flags, per-dir wait. No atomics, dirs decoupled.
__global__ void __launch_bounds__(256) lstm_kernel(
    const float* __restrict__ h0, const float* __restrict__ c0,
    const float* __restrict__ whf, const float* __restrict__ whb)
{
    extern __shared__ float sm[];
    float* Ws = sm;                 // [384][32]
    float* Hs = sm + 384 * 32;      // [384][64]

    int tile = blockIdx.x;
    int dir = tile / 48;
    int ug = tile % 48;                   // units [ug*8, ug*8+8)
    const float* W = dir ? whb : whf;

    int tid = threadIdx.x;
    int row = tid & 63;                   // batch
    int cg = tid >> 6;                    // 0..3, owns cols [cg*8, cg*8+8)

    // ---- one-time weight preload: col c -> W row (c&3)*384 + ug*8 + (c>>2)
    {
        int c = tid & 31;
        int kg = tid >> 5;                // 0..7, k range kg*48..+47
        int wr = (c & 3) * LHD + ug * 8 + (c >> 2);
        const float* src = W + (size_t)wr * LHD + kg * 48;
#pragma unroll
        for (int i = 0; i < 12; i++) {
            float4 v = *(const float4*)(src + i * 4);
            int k = kg * 48 + i * 4;
            Ws[(k + 0) * 32 + c] = v.x;
            Ws[(k + 1) * 32 + c] = v.y;
            Ws[(k + 2) * 32 + c] = v.z;
            Ws[(k + 3) * 32 + c] = v.w;
        }
    }

    // c-state lives in registers: this thread owns units j0=ug*8+cg*2, j0+1
    int j0 = ug * 8 + cg * 2;
    float creg0 = c0[((size_t)dir * BB + row) * LHD + j0];
    float creg1 = c0[((size_t)dir * BB + row) * LHD + j0 + 1];

    for (int s = 0; s < TT; s++) {
        int t = dir ? (TT - 1 - s) : s;
        int tp = dir ? (t + 1) : (t - 1);

        // ---- prefetch x gates for this thread (8 coalesced LDG, hidden
        //      behind the flag wait + H load)
        float xv[8];
        {
            const float* xb = g_X + ((size_t)(dir * TT + t)) * G4 * BB;
#pragma unroll
            for (int u = 0; u < 2; u++)
#pragma unroll
                for (int g = 0; g < 4; g++)
                    xv[u * 4 + g] = xb[((size_t)g * LHD + j0 + u) * BB + row];
        }

        // ---- wait for this dir's previous step, then load full H into smem
        if (s == 0) {
            int b = tid & 63;
            int kbase = (tid >> 6) * 96;
            const float* h0b = h0 + ((size_t)dir * BB + b) * LHD + kbase;
#pragma unroll
            for (int i = 0; i < 24; i++) {
                float4 v = *(const float4*)(h0b + i * 4);
                int k = kbase + i * 4;
                Hs[(k + 0) * 64 + b] = v.x;
                Hs[(k + 1) * 64 + b] = v.y;
                Hs[(k + 2) * 64 + b] = v.z;
                Hs[(k + 3) * 64 + b] = v.w;
            }
        } else {
            if (tid < 48) {
                while (g_flag[dir * 48 + tid] < s) { }
            }
            __syncthreads();
            __threadfence();
            const float* hp = g_Hseq + (((size_t)dir * TT + tp) * LHD) * BB;
#pragma unroll
            for (int i = 0; i < 24; i++) {
                int f = tid + i * 256;
                int k = f >> 4;
                int b4 = (f & 15) * 4;
                float4 v = *(const float4*)&hp[k * 64 + b4];
                *(float4*)&Hs[k * 64 + b4] = v;
            }
        }
        __syncthreads();

        // ---- h_{t-1} @ W_hh slice: 384 k, 8 cols per thread
        float2 acc[4];
#pragma unroll
        for (int p = 0; p < 4; p++) acc[p] = make_float2(0.f, 0.f);

        const float* wbase = Ws + cg * 8;
#pragma unroll 8
        for (int k = 0; k < 384; k++) {
            float a = Hs[k * 64 + row];
            float2 aa = make_float2(a, a);
            float4 w0 = *(const float4*)&wbase[k * 32];
            float4 w1 = *(const float4*)&wbase[k * 32 + 4];
            acc[0] = ffma2(aa, make_float2(w0.x, w0.y), acc[0]);
            acc[1] = ffma2(aa, make_float2(w0.z, w0.w), acc[1]);
            acc[2] = ffma2(aa, make_float2(w1.x, w1.y), acc[2]);
            acc[3] = ffma2(aa, make_float2(w1.z, w1.w), acc[3]);
        }

        // ---- epilogue: 2 units, gates (i,f)=acc[2u], (g,o)=acc[2u+1]
        float* hout = g_Hseq + (((size_t)dir * TT + t) * LHD) * BB;
        {
            float gi = acc[0].x + xv[0];
            float gf = acc[0].y + xv[1];
            float gg = acc[1].x + xv[2];
            float go = acc[1].y + xv[3];
            creg0 = sigm(gf) * creg0 + sigm(gi) * tanhf(gg);
            hout[(size_t)j0 * BB + row] = sigm(go) * tanhf(creg0);
        }
        {
            float gi = acc[2].x + xv[4];
            float gf = acc[2].y + xv[5];
            float gg = acc[3].x + xv[6];
            float go = acc[3].y + xv[7];
            creg1 = sigm(gf) * creg1 + sigm(gi) * tanhf(gg);
            hout[((size_t)j0 + 1) * BB + row] = sigm(go) * tanhf(creg1);
        }

        // ---- release: make H visible, then publish step completion
        __threadfence();
        __syncthreads();
        if (tid == 0) g_flag[tile] = s + 1;
    }
}

// ---------------- kernel C: FC emissions -------------------------------------
__global__ void __launch_bounds__(256) fc_kernel(
    const float* __restrict__ fcw, const float* __restrict__ fcb)
{
    __shared__ float Wsm[NLAB * 768];
    __shared__ float Bsm[NLAB];

    int t = blockIdx.x;
    int tid = threadIdx.x;
    for (int i = tid; i < NLAB * 768; i += 256) Wsm[i] = fcw[i];
    if (tid < NLAB) Bsm[tid] = fcb[tid];
    __syncthreads();

    int b = tid & 63;
    int lg = tid >> 6;  // 3 labels each
    float acc[3];
#pragma unroll
    for (int q = 0; q < 3; q++) acc[q] = Bsm[lg * 3 + q];

    const float* hf = g_Hseq + ((size_t)0 * TT + t) * LHD * BB;
    const float* hb = g_Hseq + ((size_t)1 * TT + t) * LHD * BB;
    for (int j = 0; j < LHD; j++) {
        float vf = hf[j * BB + b];
        float vb = hb[j * BB + b];
#pragma unroll
        for (int q = 0; q < 3; q++) {
            int l = lg * 3 + q;
            acc[q] += vf * Wsm[l * 768 + j] + vb * Wsm[l * 768 + LHD + j];
        }
    }
#pragma unroll
    for (int q = 0; q < 3; q++)
        g_feats[((size_t)b * TT + t) * NLAB + lg * 3 + q] = acc[q];
}

// ---------------- kernel D: Viterbi ------------------------------------------
__global__ void __launch_bounds__(128) viterbi_kernel(
    const float* __restrict__ trans, const int* __restrict__ start_ptr,
    float* __restrict__ out)
{
    __shared__ float sf[TT * NLAB];
    __shared__ float ts[NLAB * NLAB];
    __shared__ float fv[NLAB];
    __shared__ unsigned char ptr[TT * NLAB];

    int b = blockIdx.x;
    int tid = threadIdx.x;
    for (int i = tid; i < TT * NLAB; i += 128) sf[i] = g_feats[(size_t)b * TT * NLAB + i];
    for (int i = tid; i < NLAB * NLAB; i += 128) ts[i] = trans[i];
    int start = *start_ptr;
    if (tid < NLAB) fv[tid] = (tid == start) ? 0.0f : NEGV;
    __syncthreads();

    if (tid < 32) {
        for (int t = 1; t < TT; t++) {
            float best = 0.0f; int arg = 0;
            if (tid < NLAB) {
                best = ts[tid * NLAB + 0] + fv[0]; arg = 0;
#pragma unroll
                for (int p = 1; p < NLAB; p++) {
                    float v = ts[tid * NLAB + p] + fv[p];
                    if (v > best) { best = v; arg = p; }
                }
                best += sf[t * NLAB + tid];
            }
            __syncwarp();
            if (tid < NLAB) {
                fv[tid] = best;
                ptr[t * NLAB + tid] = (unsigned char)arg;
            }
            __syncwarp();
        }
        if (tid == 0) {
            float bs = fv[0]; int last = 0;
            for (int l = 1; l < NLAB; l++)
                if (fv[l] > bs) { bs = fv[l]; last = l; }
            out[b] = bs;
            float* pp = out + 64 + (size_t)b * TT;
            int cur = last;
            pp[TT - 1] = (float)cur;
            for (int t = TT - 2; t >= 0; t--) {
                cur = ptr[(t + 1) * NLAB + cur];
                pp[t] = (float)cur;
            }
        }
    }
}

// ---------------- launch ------------------------------------------------------
extern "C" void kernel_launch(void* const* d_in, const int* in_sizes, int n_in,
                              void* d_out, int out_size)
{
    const float* hidden = (const float*)d_in[0];
    const float* h0     = (const float*)d_in[1];
    const float* c0     = (const float*)d_in[2];
    const float* w_ih_f = (const float*)d_in[3];
    const float* w_hh_f = (const float*)d_in[4];
    const float* b_ih_f = (const float*)d_in[5];
    const float* b_hh_f = (const float*)d_in[6];
    const float* w_ih_b = (const float*)d_in[7];
    const float* w_hh_b = (const float*)d_in[8];
    const float* b_ih_b = (const float*)d_in[9];
    const float* b_hh_b = (const float*)d_in[10];
    const float* fc_w   = (const float*)d_in[11];
    const float* fc_b   = (const float*)d_in[12];
    const float* transitions = (const float*)d_in[13];
    const int*   start_idx   = (const int*)d_in[14];

    static int smem_set = 0;
    int lstm_smem = (384 * 32 + 384 * 64) * sizeof(float);  // 147456
    if (!smem_set) {
        cudaFuncSetAttribute(lstm_kernel,
                             cudaFuncAttributeMaxDynamicSharedMemorySize,
                             lstm_smem);
        smem_set = 1;
    }

    dim3 gridA(12, 512, 2);
    proj_kernel<<<gridA, 256>>>(hidden, w_ih_f, w_ih_b,
                                b_ih_f, b_hh_f, b_ih_b, b_hh_b);
    reset_flags_kernel<<<1, 128>>>();
    lstm_kernel<<<NBLK_LSTM, 256, lstm_smem>>>(h0, c0, w_hh_f, w_hh_b);
    fc_kernel<<<512, 256>>>(fc_w, fc_b);
    viterbi_kernel<<<64, 128>>>(transitions, start_idx, (float*)d_out);
}

// round 9
// speedup vs baseline: 1.3246x; 1.3246x over previous
#include <cuda_runtime.h>
#include <cuda_bf16.h>
#include <cstdint>

// Problem constants
#define TT 512
#define BB 64
#define HH 768
#define LHD 384
#define G4 1536
#define NLAB 12
#define NEGV (-1000.0f)
#define NBLK_LSTM 96

// ---------------- scratch (static device memory; no allocation) -------------
// X[dir][t][col][b], col = gate*384 + j
__device__ float g_X[100663296];
// Hseq[dir][t][j][b]
__device__ float g_Hseq[25165824];
// feats[b][t][l]
__device__ float g_feats[64 * 512 * 12];
// per-CTA step-completion flags
__device__ volatile int g_flag[NBLK_LSTM];
// bf16 split of W_ih: [dir][split(hi/lo)][1536][768]
__device__ __align__(16) __nv_bfloat16 g_Wsp[2 * 2 * 1536 * 768];
// bf16 split of hidden: [t][split][b][768]
__device__ __align__(16) __nv_bfloat16 g_Hsp[512 * 2 * 64 * 768];

__device__ __forceinline__ float sigm(float x) {
    return 1.0f / (1.0f + __expf(-x));
}

// packed f32x2 FMA
__device__ __forceinline__ float2 ffma2(float2 a, float2 b, float2 c) {
    union U { float2 f; unsigned long long u; };
    U A, B, C, D;
    A.f = a; B.f = b; C.f = c;
    asm("fma.rn.f32x2 %0, %1, %2, %3;"
        : "=l"(D.u) : "l"(A.u), "l"(B.u), "l"(C.u));
    return D.f;
}

// warp-level bf16 tensor-core MMA (sm_80+ PTX, no 'a'-suffix features)
__device__ __forceinline__ void mma_bf16(
    float& c0, float& c1, float& c2, float& c3,
    uint32_t a0, uint32_t a1, uint32_t a2, uint32_t a3,
    uint32_t b0, uint32_t b1)
{
    asm volatile(
        "mma.sync.aligned.m16n8k16.row.col.f32.bf16.bf16.f32 "
        "{%0,%1,%2,%3}, {%4,%5,%6,%7}, {%8,%9}, {%0,%1,%2,%3};"
        : "+f"(c0), "+f"(c1), "+f"(c2), "+f"(c3)
        : "r"(a0), "r"(a1), "r"(a2), "r"(a3), "r"(b0), "r"(b1));
}

// ---------------- split kernels: fp32 -> bf16 hi/lo --------------------------
__global__ void __launch_bounds__(256) split_w_kernel(
    const float* __restrict__ wf, const float* __restrict__ wb)
{
    int col = blockIdx.x;
    int dir = blockIdx.y;
    const float* src = dir ? wb : wf;
    int tid = threadIdx.x;
#pragma unroll
    for (int i = 0; i < 3; i++) {
        int k = i * 256 + tid;
        float x = src[(size_t)col * HH + k];
        __nv_bfloat16 hi = __float2bfloat16(x);
        __nv_bfloat16 lo = __float2bfloat16(x - __bfloat162float(hi));
        g_Wsp[((size_t)(dir * 2 + 0) * G4 + col) * HH + k] = hi;
        g_Wsp[((size_t)(dir * 2 + 1) * G4 + col) * HH + k] = lo;
    }
}

__global__ void __launch_bounds__(256) split_h_kernel(
    const float* __restrict__ hid)
{
    int t = blockIdx.x;
    int b0 = blockIdx.y * 8;
    int tid = threadIdx.x;
    for (int bo = 0; bo < 8; bo++) {
        int b = b0 + bo;
#pragma unroll
        for (int i = 0; i < 3; i++) {
            int k = i * 256 + tid;
            float x = hid[((size_t)b * TT + t) * HH + k];
            __nv_bfloat16 hi = __float2bfloat16(x);
            __nv_bfloat16 lo = __float2bfloat16(x - __bfloat162float(hi));
            g_Hsp[((size_t)(t * 2 + 0) * BB + b) * HH + k] = hi;
            g_Hsp[((size_t)(t * 2 + 1) * BB + b) * HH + k] = lo;
        }
    }
}

// ---------------- kernel A: projection GEMM on mma.sync tensor cores --------
// D[m=col 0..127][n = tl*64+b, 0..127] = sum over K=768 x 3 split terms of
//   Wsp[dir][spA][cb+m][k] * Hsp[t0+tl][spB][b][k]
// CTA tile 128x128, 8 warps (2m x 4n), warp tile 64x32, m16n8k16 frags.
__global__ void __launch_bounds__(256) proj_mma_kernel(
    const float* __restrict__ bif, const float* __restrict__ bhf,
    const float* __restrict__ bib, const float* __restrict__ bhb)
{
    __shared__ __nv_bfloat16 Asm[128][40];   // [m][k], pad 40
    __shared__ __nv_bfloat16 Bsm[128][40];   // [n][k], pad 40

    int ct  = blockIdx.x;          // col tile 0..11
    int dir = blockIdx.y;
    int tg  = blockIdx.z;          // t-group 0..255 (2 t each)
    int cb  = ct * 128;
    int t0  = tg * 2;

    int tid  = threadIdx.x;
    int lane = tid & 31;
    int warp = tid >> 5;
    int wm = (warp >> 2) * 64;     // warp m offset 0 / 64
    int wn = (warp & 3) * 32;      // warp n offset 0,32,64,96

    float acc[4][4][4];
#pragma unroll
    for (int mi = 0; mi < 4; mi++)
#pragma unroll
        for (int ni = 0; ni < 4; ni++)
#pragma unroll
            for (int q = 0; q < 4; q++) acc[mi][ni][q] = 0.0f;

    // bias per owned m row
    const float* b1 = dir ? bib : bif;
    const float* b2 = dir ? bhb : bhf;
    float bias0[4], bias1[4];
#pragma unroll
    for (int mi = 0; mi < 4; mi++) {
        int m0 = wm + mi * 16 + (lane >> 2);
        bias0[mi] = b1[cb + m0] + b2[cb + m0];
        bias1[mi] = b1[cb + m0 + 8] + b2[cb + m0 + 8];
    }

    // loaders: thread covers row r = tid>>1, 16 k at seg*16
    int r = tid >> 1;
    int seg = tid & 1;
    int tlL = r >> 6;
    int bbL = r & 63;

    for (int term = 0; term < 3; term++) {
        int spA = (term == 2) ? 1 : 0;
        int spB = (term == 1) ? 1 : 0;
        const __nv_bfloat16* Abase = g_Wsp +
            ((size_t)(dir * 2 + spA) * G4 + cb + r) * HH + seg * 16;
        const __nv_bfloat16* Bbase = g_Hsp +
            ((size_t)((t0 + tlL) * 2 + spB) * BB + bbL) * HH + seg * 16;

        for (int kc = 0; kc < 24; kc++) {
            uint4 av0 = *(const uint4*)(Abase + kc * 32);
            uint4 av1 = *(const uint4*)(Abase + kc * 32 + 8);
            uint4 bv0 = *(const uint4*)(Bbase + kc * 32);
            uint4 bv1 = *(const uint4*)(Bbase + kc * 32 + 8);
            __syncthreads();   // previous chunk's compute done
            *(uint4*)&Asm[r][seg * 16]     = av0;
            *(uint4*)&Asm[r][seg * 16 + 8] = av1;
            *(uint4*)&Bsm[r][seg * 16]     = bv0;
            *(uint4*)&Bsm[r][seg * 16 + 8] = bv1;
            __syncthreads();

#pragma unroll
            for (int ks = 0; ks < 2; ks++) {
                int gk = ks * 16 + (lane & 3) * 2;
                uint32_t ar[4][4];
#pragma unroll
                for (int mi = 0; mi < 4; mi++) {
                    int gm = wm + mi * 16 + (lane >> 2);
                    ar[mi][0] = *(const uint32_t*)&Asm[gm][gk];
                    ar[mi][1] = *(const uint32_t*)&Asm[gm + 8][gk];
                    ar[mi][2] = *(const uint32_t*)&Asm[gm][gk + 8];
                    ar[mi][3] = *(const uint32_t*)&Asm[gm + 8][gk + 8];
                }
#pragma unroll
                for (int ni = 0; ni < 4; ni++) {
                    int gn = wn + ni * 8 + (lane >> 2);
                    uint32_t br0 = *(const uint32_t*)&Bsm[gn][gk];
                    uint32_t br1 = *(const uint32_t*)&Bsm[gn][gk + 8];
#pragma unroll
                    for (int mi = 0; mi < 4; mi++)
                        mma_bf16(acc[mi][ni][0], acc[mi][ni][1],
                                 acc[mi][ni][2], acc[mi][ni][3],
                                 ar[mi][0], ar[mi][1], ar[mi][2], ar[mi][3],
                                 br0, br1);
                }
            }
        }
    }

    // epilogue: c0,c1 = (m0, n..n+1); c2,c3 = (m0+8, n..n+1)
#pragma unroll
    for (int mi = 0; mi < 4; mi++) {
#pragma unroll
        for (int ni = 0; ni < 4; ni++) {
            int m0 = wm + mi * 16 + (lane >> 2);
            int n = wn + ni * 8 + (lane & 3) * 2;
            int tl = n >> 6;
            int bb = n & 63;
            float* op = g_X +
                (((size_t)dir * TT + t0 + tl) * G4 + cb) * BB;
            float2 v0, v1;
            v0.x = acc[mi][ni][0] + bias0[mi];
            v0.y = acc[mi][ni][1] + bias0[mi];
            v1.x = acc[mi][ni][2] + bias1[mi];
            v1.y = acc[mi][ni][3] + bias1[mi];
            *(float2*)&op[(size_t)m0 * BB + bb] = v0;
            *(float2*)&op[(size_t)(m0 + 8) * BB + bb] = v1;
        }
    }
}

// ---------------- reset flags -------------------------------------------------
__global__ void reset_flags_kernel() {
    if (threadIdx.x < NBLK_LSTM) g_flag[threadIdx.x] = 0;
}

// ---------------- kernel B: persistent BiLSTM recurrence ---------------------
__global__ void __launch_bounds__(256) lstm_kernel(
    const float* __restrict__ h0, const float* __restrict__ c0,
    const float* __restrict__ whf, const float* __restrict__ whb)
{
    extern __shared__ float sm[];
    float* Ws = sm;                 // [384][32]
    float* Hs = sm + 384 * 32;      // [384][64]

    int tile = blockIdx.x;
    int dir = tile / 48;
    int ug = tile % 48;
    const float* W = dir ? whb : whf;

    int tid = threadIdx.x;
    int row = tid & 63;
    int cg = tid >> 6;

    {
        int c = tid & 31;
        int kg = tid >> 5;
        int wr = (c & 3) * LHD + ug * 8 + (c >> 2);
        const float* src = W + (size_t)wr * LHD + kg * 48;
#pragma unroll
        for (int i = 0; i < 12; i++) {
            float4 v = *(const float4*)(src + i * 4);
            int k = kg * 48 + i * 4;
            Ws[(k + 0) * 32 + c] = v.x;
            Ws[(k + 1) * 32 + c] = v.y;
            Ws[(k + 2) * 32 + c] = v.z;
            Ws[(k + 3) * 32 + c] = v.w;
        }
    }

    int j0 = ug * 8 + cg * 2;
    float creg0 = c0[((size_t)dir * BB + row) * LHD + j0];
    float creg1 = c0[((size_t)dir * BB + row) * LHD + j0 + 1];

    for (int s = 0; s < TT; s++) {
        int t = dir ? (TT - 1 - s) : s;
        int tp = dir ? (t + 1) : (t - 1);

        float xv[8];
        {
            const float* xb = g_X + ((size_t)(dir * TT + t)) * G4 * BB;
#pragma unroll
            for (int u = 0; u < 2; u++)
#pragma unroll
                for (int g = 0; g < 4; g++)
                    xv[u * 4 + g] = xb[((size_t)g * LHD + j0 + u) * BB + row];
        }

        if (s == 0) {
            int b = tid & 63;
            int kbase = (tid >> 6) * 96;
            const float* h0b = h0 + ((size_t)dir * BB + b) * LHD + kbase;
#pragma unroll
            for (int i = 0; i < 24; i++) {
                float4 v = *(const float4*)(h0b + i * 4);
                int k = kbase + i * 4;
                Hs[(k + 0) * 64 + b] = v.x;
                Hs[(k + 1) * 64 + b] = v.y;
                Hs[(k + 2) * 64 + b] = v.z;
                Hs[(k + 3) * 64 + b] = v.w;
            }
        } else {
            if (tid < 48) {
                while (g_flag[dir * 48 + tid] < s) { }
            }
            __syncthreads();
            __threadfence();
            const float* hp = g_Hseq + (((size_t)dir * TT + tp) * LHD) * BB;
#pragma unroll
            for (int i = 0; i < 24; i++) {
                int f = tid + i * 256;
                int k = f >> 4;
                int b4 = (f & 15) * 4;
                float4 v = *(const float4*)&hp[k * 64 + b4];
                *(float4*)&Hs[k * 64 + b4] = v;
            }
        }
        __syncthreads();

        float2 acc[4];
#pragma unroll
        for (int p = 0; p < 4; p++) acc[p] = make_float2(0.f, 0.f);

        const float* wbase = Ws + cg * 8;
#pragma unroll 8
        for (int k = 0; k < 384; k++) {
            float a = Hs[k * 64 + row];
            float2 aa = make_float2(a, a);
            float4 w0 = *(const float4*)&wbase[k * 32];
            float4 w1 = *(const float4*)&wbase[k * 32 + 4];
            acc[0] = ffma2(aa, make_float2(w0.x, w0.y), acc[0]);
            acc[1] = ffma2(aa, make_float2(w0.z, w0.w), acc[1]);
            acc[2] = ffma2(aa, make_float2(w1.x, w1.y), acc[2]);
            acc[3] = ffma2(aa, make_float2(w1.z, w1.w), acc[3]);
        }

        float* hout = g_Hseq + (((size_t)dir * TT + t) * LHD) * BB;
        {
            float gi = acc[0].x + xv[0];
            float gf = acc[0].y + xv[1];
            float gg = acc[1].x + xv[2];
            float go = acc[1].y + xv[3];
            creg0 = sigm(gf) * creg0 + sigm(gi) * tanhf(gg);
            hout[(size_t)j0 * BB + row] = sigm(go) * tanhf(creg0);
        }
        {
            float gi = acc[2].x + xv[4];
            float gf = acc[2].y + xv[5];
            float gg = acc[3].x + xv[6];
            float go = acc[3].y + xv[7];
            creg1 = sigm(gf) * creg1 + sigm(gi) * tanhf(gg);
            hout[((size_t)j0 + 1) * BB + row] = sigm(go) * tanhf(creg1);
        }

        __threadfence();
        __syncthreads();
        if (tid == 0) g_flag[tile] = s + 1;
    }
}

// ---------------- kernel C: FC emissions -------------------------------------
__global__ void __launch_bounds__(256) fc_kernel(
    const float* __restrict__ fcw, const float* __restrict__ fcb)
{
    __shared__ float Wsm[NLAB * 768];
    __shared__ float Bsm[NLAB];

    int t = blockIdx.x;
    int tid = threadIdx.x;
    for (int i = tid; i < NLAB * 768; i += 256) Wsm[i] = fcw[i];
    if (tid < NLAB) Bsm[tid] = fcb[tid];
    __syncthreads();

    int b = tid & 63;
    int lg = tid >> 6;
    float acc[3];
#pragma unroll
    for (int q = 0; q < 3; q++) acc[q] = Bsm[lg * 3 + q];

    const float* hf = g_Hseq + ((size_t)0 * TT + t) * LHD * BB;
    const float* hb = g_Hseq + ((size_t)1 * TT + t) * LHD * BB;
    for (int j = 0; j < LHD; j++) {
        float vf = hf[j * BB + b];
        float vb = hb[j * BB + b];
#pragma unroll
        for (int q = 0; q < 3; q++) {
            int l = lg * 3 + q;
            acc[q] += vf * Wsm[l * 768 + j] + vb * Wsm[l * 768 + LHD + j];
        }
    }
#pragma unroll
    for (int q = 0; q < 3; q++)
        g_feats[((size_t)b * TT + t) * NLAB + lg * 3 + q] = acc[q];
}

// ---------------- kernel D: Viterbi ------------------------------------------
__global__ void __launch_bounds__(128) viterbi_kernel(
    const float* __restrict__ trans, const int* __restrict__ start_ptr,
    float* __restrict__ out)
{
    __shared__ float sf[TT * NLAB];
    __shared__ float ts[NLAB * NLAB];
    __shared__ float fv[NLAB];
    __shared__ unsigned char ptr[TT * NLAB];

    int b = blockIdx.x;
    int tid = threadIdx.x;
    for (int i = tid; i < TT * NLAB; i += 128) sf[i] = g_feats[(size_t)b * TT * NLAB + i];
    for (int i = tid; i < NLAB * NLAB; i += 128) ts[i] = trans[i];
    int start = *start_ptr;
    if (tid < NLAB) fv[tid] = (tid == start) ? 0.0f : NEGV;
    __syncthreads();

    if (tid < 32) {
        for (int t = 1; t < TT; t++) {
            float best = 0.0f; int arg = 0;
            if (tid < NLAB) {
                best = ts[tid * NLAB + 0] + fv[0]; arg = 0;
#pragma unroll
                for (int p = 1; p < NLAB; p++) {
                    float v = ts[tid * NLAB + p] + fv[p];
                    if (v > best) { best = v; arg = p; }
                }
                best += sf[t * NLAB + tid];
            }
            __syncwarp();
            if (tid < NLAB) {
                fv[tid] = best;
                ptr[t * NLAB + tid] = (unsigned char)arg;
            }
            __syncwarp();
        }
        if (tid == 0) {
            float bs = fv[0]; int last = 0;
            for (int l = 1; l < NLAB; l++)
                if (fv[l] > bs) { bs = fv[l]; last = l; }
            out[b] = bs;
            float* pp = out + 64 + (size_t)b * TT;
            int cur = last;
            pp[TT - 1] = (float)cur;
            for (int t = TT - 2; t >= 0; t--) {
                cur = ptr[(t + 1) * NLAB + cur];
                pp[t] = (float)cur;
            }
        }
    }
}

// ---------------- launch ------------------------------------------------------
extern "C" void kernel_launch(void* const* d_in, const int* in_sizes, int n_in,
                              void* d_out, int out_size)
{
    const float* hidden = (const float*)d_in[0];
    const float* h0     = (const float*)d_in[1];
    const float* c0     = (const float*)d_in[2];
    const float* w_ih_f = (const float*)d_in[3];
    const float* w_hh_f = (const float*)d_in[4];
    const float* b_ih_f = (const float*)d_in[5];
    const float* b_hh_f = (const float*)d_in[6];
    const float* w_ih_b = (const float*)d_in[7];
    const float* w_hh_b = (const float*)d_in[8];
    const float* b_ih_b = (const float*)d_in[9];
    const float* b_hh_b = (const float*)d_in[10];
    const float* fc_w   = (const float*)d_in[11];
    const float* fc_b   = (const float*)d_in[12];
    const float* transitions = (const float*)d_in[13];
    const int*   start_idx   = (const int*)d_in[14];

    static int attr_set = 0;
    int lstm_smem = (384 * 32 + 384 * 64) * sizeof(float);  // 147456
    if (!attr_set) {
        cudaFuncSetAttribute(lstm_kernel,
                             cudaFuncAttributeMaxDynamicSharedMemorySize,
                             lstm_smem);
        attr_set = 1;
    }

    split_w_kernel<<<dim3(1536, 2), 256>>>(w_ih_f, w_ih_b);
    split_h_kernel<<<dim3(512, 8), 256>>>(hidden);
    proj_mma_kernel<<<dim3(12, 2, 256), 256>>>(b_ih_f, b_hh_f,
                                                b_ih_b, b_hh_b);
    reset_flags_kernel<<<1, 128>>>();
    lstm_kernel<<<NBLK_LSTM, 256, lstm_smem>>>(h0, c0, w_hh_f, w_hh_b);
    fc_kernel<<<512, 256>>>(fc_w, fc_b);
    viterbi_kernel<<<64, 128>>>(transitions, start_idx, (float*)d_out);
}

// round 13
// speedup vs baseline: 1.5723x; 1.1870x over previous
#include <cuda_runtime.h>
#include <cuda_bf16.h>
#include <cstdint>

// Problem constants
#define TT 512
#define BB 64
#define HH 768
#define LHD 384
#define G4 1536
#define NLAB 12
#define NEGV (-1000.0f)
#define NBLK_LSTM 96

// ---------------- scratch (static device memory; no allocation) -------------
// X[dir][t][col][b], col = gate*384 + j
__device__ float g_X[100663296];
// Hseq[dir][t][j][b]
__device__ float g_Hseq[25165824];
// feats[b][t][l]
__device__ float g_feats[64 * 512 * 12];
// per-CTA step-completion flags
__device__ volatile int g_flag[NBLK_LSTM];
// bf16 split of W_ih: [dir][split(hi/lo)][1536][768]
__device__ __align__(16) __nv_bfloat16 g_Wsp[2 * 2 * 1536 * 768];
// bf16 split of hidden: [t][split][b][768]
__device__ __align__(16) __nv_bfloat16 g_Hsp[512 * 2 * 64 * 768];
// double-buffered bf16 split of recurrent h: [buf][dir][split][b][384]
__device__ __align__(16) __nv_bfloat16 g_hrec[2 * 2 * 2 * 64 * 384];

__device__ __forceinline__ float sigm(float x) {
    return 1.0f / (1.0f + __expf(-x));
}

// warp-level bf16 tensor-core MMA (sm_80+ PTX, no 'a'-suffix features)
__device__ __forceinline__ void mma_bf16(
    float& c0, float& c1, float& c2, float& c3,
    uint32_t a0, uint32_t a1, uint32_t a2, uint32_t a3,
    uint32_t b0, uint32_t b1)
{
    asm volatile(
        "mma.sync.aligned.m16n8k16.row.col.f32.bf16.bf16.f32 "
        "{%0,%1,%2,%3}, {%4,%5,%6,%7}, {%8,%9}, {%0,%1,%2,%3};"
        : "+f"(c0), "+f"(c1), "+f"(c2), "+f"(c3)
        : "r"(a0), "r"(a1), "r"(a2), "r"(a3), "r"(b0), "r"(b1));
}

// ---------------- split kernels: fp32 -> bf16 hi/lo --------------------------
__global__ void __launch_bounds__(256) split_w_kernel(
    const float* __restrict__ wf, const float* __restrict__ wb)
{
    int col = blockIdx.x;
    int dir = blockIdx.y;
    const float* src = dir ? wb : wf;
    int tid = threadIdx.x;
#pragma unroll
    for (int i = 0; i < 3; i++) {
        int k = i * 256 + tid;
        float x = src[(size_t)col * HH + k];
        __nv_bfloat16 hi = __float2bfloat16(x);
        __nv_bfloat16 lo = __float2bfloat16(x - __bfloat162float(hi));
        g_Wsp[((size_t)(dir * 2 + 0) * G4 + col) * HH + k] = hi;
        g_Wsp[((size_t)(dir * 2 + 1) * G4 + col) * HH + k] = lo;
    }
}

__global__ void __launch_bounds__(256) split_h_kernel(
    const float* __restrict__ hid)
{
    int t = blockIdx.x;
    int b0 = blockIdx.y * 8;
    int tid = threadIdx.x;
    for (int bo = 0; bo < 8; bo++) {
        int b = b0 + bo;
#pragma unroll
        for (int i = 0; i < 3; i++) {
            int k = i * 256 + tid;
            float x = hid[((size_t)b * TT + t) * HH + k];
            __nv_bfloat16 hi = __float2bfloat16(x);
            __nv_bfloat16 lo = __float2bfloat16(x - __bfloat162float(hi));
            g_Hsp[((size_t)(t * 2 + 0) * BB + b) * HH + k] = hi;
            g_Hsp[((size_t)(t * 2 + 1) * BB + b) * HH + k] = lo;
        }
    }
}

// ---------------- kernel A: projection GEMM on mma.sync tensor cores --------
__global__ void __launch_bounds__(256) proj_mma_kernel(
    const float* __restrict__ bif, const float* __restrict__ bhf,
    const float* __restrict__ bib, const float* __restrict__ bhb)
{
    __shared__ __nv_bfloat16 Asm[128][40];
    __shared__ __nv_bfloat16 Bsm[128][40];

    int ct  = blockIdx.x;
    int dir = blockIdx.y;
    int tg  = blockIdx.z;
    int cb  = ct * 128;
    int t0  = tg * 2;

    int tid  = threadIdx.x;
    int lane = tid & 31;
    int warp = tid >> 5;
    int wm = (warp >> 2) * 64;
    int wn = (warp & 3) * 32;

    float acc[4][4][4];
#pragma unroll
    for (int mi = 0; mi < 4; mi++)
#pragma unroll
        for (int ni = 0; ni < 4; ni++)
#pragma unroll
            for (int q = 0; q < 4; q++) acc[mi][ni][q] = 0.0f;

    const float* b1 = dir ? bib : bif;
    const float* b2 = dir ? bhb : bhf;
    float bias0[4], bias1[4];
#pragma unroll
    for (int mi = 0; mi < 4; mi++) {
        int m0 = wm + mi * 16 + (lane >> 2);
        bias0[mi] = b1[cb + m0] + b2[cb + m0];
        bias1[mi] = b1[cb + m0 + 8] + b2[cb + m0 + 8];
    }

    int r = tid >> 1;
    int seg = tid & 1;
    int tlL = r >> 6;
    int bbL = r & 63;

    for (int term = 0; term < 3; term++) {
        int spA = (term == 2) ? 1 : 0;
        int spB = (term == 1) ? 1 : 0;
        const __nv_bfloat16* Abase = g_Wsp +
            ((size_t)(dir * 2 + spA) * G4 + cb + r) * HH + seg * 16;
        const __nv_bfloat16* Bbase = g_Hsp +
            ((size_t)((t0 + tlL) * 2 + spB) * BB + bbL) * HH + seg * 16;

        for (int kc = 0; kc < 24; kc++) {
            uint4 av0 = *(const uint4*)(Abase + kc * 32);
            uint4 av1 = *(const uint4*)(Abase + kc * 32 + 8);
            uint4 bv0 = *(const uint4*)(Bbase + kc * 32);
            uint4 bv1 = *(const uint4*)(Bbase + kc * 32 + 8);
            __syncthreads();
            *(uint4*)&Asm[r][seg * 16]     = av0;
            *(uint4*)&Asm[r][seg * 16 + 8] = av1;
            *(uint4*)&Bsm[r][seg * 16]     = bv0;
            *(uint4*)&Bsm[r][seg * 16 + 8] = bv1;
            __syncthreads();

#pragma unroll
            for (int ks = 0; ks < 2; ks++) {
                int gk = ks * 16 + (lane & 3) * 2;
                uint32_t ar[4][4];
#pragma unroll
                for (int mi = 0; mi < 4; mi++) {
                    int gm = wm + mi * 16 + (lane >> 2);
                    ar[mi][0] = *(const uint32_t*)&Asm[gm][gk];
                    ar[mi][1] = *(const uint32_t*)&Asm[gm + 8][gk];
                    ar[mi][2] = *(const uint32_t*)&Asm[gm][gk + 8];
                    ar[mi][3] = *(const uint32_t*)&Asm[gm + 8][gk + 8];
                }
#pragma unroll
                for (int ni = 0; ni < 4; ni++) {
                    int gn = wn + ni * 8 + (lane >> 2);
                    uint32_t br0 = *(const uint32_t*)&Bsm[gn][gk];
                    uint32_t br1 = *(const uint32_t*)&Bsm[gn][gk + 8];
#pragma unroll
                    for (int mi = 0; mi < 4; mi++)
                        mma_bf16(acc[mi][ni][0], acc[mi][ni][1],
                                 acc[mi][ni][2], acc[mi][ni][3],
                                 ar[mi][0], ar[mi][1], ar[mi][2], ar[mi][3],
                                 br0, br1);
                }
            }
        }
    }

#pragma unroll
    for (int mi = 0; mi < 4; mi++) {
#pragma unroll
        for (int ni = 0; ni < 4; ni++) {
            int m0 = wm + mi * 16 + (lane >> 2);
            int n = wn + ni * 8 + (lane & 3) * 2;
            int tl = n >> 6;
            int bb = n & 63;
            float* op = g_X +
                (((size_t)dir * TT + t0 + tl) * G4 + cb) * BB;
            float2 v0, v1;
            v0.x = acc[mi][ni][0] + bias0[mi];
            v0.y = acc[mi][ni][1] + bias0[mi];
            v1.x = acc[mi][ni][2] + bias1[mi];
            v1.y = acc[mi][ni][3] + bias1[mi];
            *(float2*)&op[(size_t)m0 * BB + bb] = v0;
            *(float2*)&op[(size_t)(m0 + 8) * BB + bb] = v1;
        }
    }
}

// ---------------- prep: reset flags + split h0 into g_hrec buf 0 -------------
__global__ void __launch_bounds__(384) lstm_prep_kernel(
    const float* __restrict__ h0)
{
    int dir = blockIdx.x >> 6;
    int b   = blockIdx.x & 63;
    int u   = threadIdx.x;
    float x = h0[((size_t)(dir * BB + b)) * LHD + u];
    __nv_bfloat16 hi = __float2bfloat16(x);
    __nv_bfloat16 lo = __float2bfloat16(x - __bfloat162float(hi));
    g_hrec[((size_t)(dir * 2 + 0) * BB + b) * LHD + u] = hi;
    g_hrec[((size_t)(dir * 2 + 1) * BB + b) * LHD + u] = lo;
    if (blockIdx.x == 0 && u < NBLK_LSTM) g_flag[u] = 0;
}

// ---------------- kernel B: persistent BiLSTM recurrence (tensor cores) -----
// 96 CTAs: (dir, 32 gate-cols) x 64 batch. Warp tile M=32 x N=8, K=384, 3 terms.
// smem: A(W slice) hi/lo [32][392]x2 + B(h) hi/lo [64][392]x2 = 150528 B.
#define LPAD 392
#define A_ELEMS (32 * LPAD)
#define B_ELEMS (64 * LPAD)

__global__ void __launch_bounds__(256) lstm_mma_kernel(
    const float* __restrict__ h0, const float* __restrict__ c0,
    const float* __restrict__ whf, const float* __restrict__ whb)
{
    extern __shared__ __nv_bfloat16 smb[];
    __nv_bfloat16* AsmH = smb;
    __nv_bfloat16* AsmL = smb + A_ELEMS;
    __nv_bfloat16* BsmH = smb + 2 * A_ELEMS;
    __nv_bfloat16* BsmL = smb + 2 * A_ELEMS + B_ELEMS;

    int tile = blockIdx.x;
    int dir = tile / 48;
    int ug = tile % 48;                    // units [ug*8, ug*8+8)
    const float* W = dir ? whb : whf;

    int tid  = threadIdx.x;
    int lane = tid & 31;
    int warp = tid >> 5;

    // ---- one-time W slice preload + bf16 split
    // A row m = gate*8+u  <->  W row gate*384 + ug*8 + u
    {
        int m = tid >> 3;                  // 0..31
        int kseg = (tid & 7) * 48;
        int wrow = (m >> 3) * LHD + ug * 8 + (m & 7);
        const float* src = W + (size_t)wrow * LHD + kseg;
#pragma unroll
        for (int i = 0; i < 48; i++) {
            float x = src[i];
            __nv_bfloat16 hi = __float2bfloat16(x);
            __nv_bfloat16 lo = __float2bfloat16(x - __bfloat162float(hi));
            AsmH[m * LPAD + kseg + i] = hi;
            AsmL[m * LPAD + kseg + i] = lo;
        }
    }

    // thread ownership: unit j = ug*8 + (lane>>2), batches b0, b0+1
    int uloc = lane >> 2;
    int j = ug * 8 + uloc;
    int b0 = warp * 8 + (lane & 3) * 2;

    float cr0 = c0[((size_t)(dir * BB + b0)) * LHD + j];
    float cr1 = c0[((size_t)(dir * BB + b0 + 1)) * LHD + j];

    for (int s = 0; s < TT; s++) {
        int t = dir ? (TT - 1 - s) : s;

        // ---- prefetch x gate values (before the wait)
        float2 xv[4];
        {
            const float* xb = g_X + ((size_t)(dir * TT + t)) * G4 * BB;
#pragma unroll
            for (int g = 0; g < 4; g++)
                xv[g] = *(const float2*)&xb[((size_t)g * LHD + j) * BB + b0];
        }

        // ---- wait for previous step of this direction
        if (s > 0) {
            if (tid < 48) {
                while (g_flag[dir * 48 + tid] < s) { }
            }
        }
        __syncthreads();
        if (s > 0) __threadfence();

        // ---- load B = h split [64][384] hi+lo from g_hrec buf (s&1)
        {
            int rb = s & 1;
            const __nv_bfloat16* srcH = g_hrec +
                ((size_t)((rb * 2 + dir) * 2 + 0)) * BB * LHD;
            const __nv_bfloat16* srcL = g_hrec +
                ((size_t)((rb * 2 + dir) * 2 + 1)) * BB * LHD;
#pragma unroll
            for (int i = 0; i < 12; i++) {
                int u = tid + i * 256;       // 0..3071 uint4 of split hi
                int row = u / 48;
                int c16 = u % 48;
                uint4 v = *(const uint4*)(srcH + (size_t)row * LHD + c16 * 8);
                *(uint4*)&BsmH[row * LPAD + c16 * 8] = v;
            }
#pragma unroll
            for (int i = 0; i < 12; i++) {
                int u = tid + i * 256;
                int row = u / 48;
                int c16 = u % 48;
                uint4 v = *(const uint4*)(srcL + (size_t)row * LHD + c16 * 8);
                *(uint4*)&BsmL[row * LPAD + c16 * 8] = v;
            }
        }
        __syncthreads();

        // ---- MMA: [32 cols x 64 batch] = A[32,384] x B[64,384]^T, 3 terms
        float acc[2][4];
#pragma unroll
        for (int mi = 0; mi < 2; mi++)
#pragma unroll
            for (int q = 0; q < 4; q++) acc[mi][q] = 0.0f;

        int gn = warp * 8 + (lane >> 2);
        int klo = (lane & 3) * 2;

#pragma unroll
        for (int term = 0; term < 3; term++) {
            const __nv_bfloat16* Ab = (term == 2) ? AsmL : AsmH;
            const __nv_bfloat16* Bb = (term == 1) ? BsmL : BsmH;
#pragma unroll 4
            for (int kc = 0; kc < 24; kc++) {
                int k0 = kc * 16 + klo;
                uint32_t br0 = *(const uint32_t*)&Bb[gn * LPAD + k0];
                uint32_t br1 = *(const uint32_t*)&Bb[gn * LPAD + k0 + 8];
#pragma unroll
                for (int mi = 0; mi < 2; mi++) {
                    int m0 = mi * 16 + uloc;
                    uint32_t a0 = *(const uint32_t*)&Ab[m0 * LPAD + k0];
                    uint32_t a1 = *(const uint32_t*)&Ab[(m0 + 8) * LPAD + k0];
                    uint32_t a2 = *(const uint32_t*)&Ab[m0 * LPAD + k0 + 8];
                    uint32_t a3 = *(const uint32_t*)&Ab[(m0 + 8) * LPAD + k0 + 8];
                    mma_bf16(acc[mi][0], acc[mi][1], acc[mi][2], acc[mi][3],
                             a0, a1, a2, a3, br0, br1);
                }
            }
        }

        // ---- epilogue: mi0 c0/c1 = gate i (b0,b1), c2/c3 = gate f,
        //               mi1 c0/c1 = gate g,          c2/c3 = gate o
        int wb = (s + 1) & 1;
        __nv_bfloat16* dstH = g_hrec + ((size_t)((wb * 2 + dir) * 2 + 0)) * BB * LHD;
        __nv_bfloat16* dstL = g_hrec + ((size_t)((wb * 2 + dir) * 2 + 1)) * BB * LHD;
        float* hout = g_Hseq + (((size_t)dir * TT + t) * LHD + j) * BB;

        float h0v, h1v;
        {
            float gi = acc[0][0] + xv[0].x;
            float gf = acc[0][2] + xv[1].x;
            float gg = acc[1][0] + xv[2].x;
            float go = acc[1][2] + xv[3].x;
            cr0 = sigm(gf) * cr0 + sigm(gi) * tanhf(gg);
            h0v = sigm(go) * tanhf(cr0);
        }
        {
            float gi = acc[0][1] + xv[0].y;
            float gf = acc[0][3] + xv[1].y;
            float gg = acc[1][1] + xv[2].y;
            float go = acc[1][3] + xv[3].y;
            cr1 = sigm(gf) * cr1 + sigm(gi) * tanhf(gg);
            h1v = sigm(go) * tanhf(cr1);
        }

        *(float2*)&hout[b0] = make_float2(h0v, h1v);
        {
            __nv_bfloat16 hi0 = __float2bfloat16(h0v);
            __nv_bfloat16 lo0 = __float2bfloat16(h0v - __bfloat162float(hi0));
            __nv_bfloat16 hi1 = __float2bfloat16(h1v);
            __nv_bfloat16 lo1 = __float2bfloat16(h1v - __bfloat162float(hi1));
            dstH[(size_t)b0 * LHD + j] = hi0;
            dstH[(size_t)(b0 + 1) * LHD + j] = hi1;
            dstL[(size_t)b0 * LHD + j] = lo0;
            dstL[(size_t)(b0 + 1) * LHD + j] = lo1;
        }

        // ---- release
        __threadfence();
        __syncthreads();
        if (tid == 0) g_flag[tile] = s + 1;
    }
}

// ---------------- kernel C: FC emissions -------------------------------------
__global__ void __launch_bounds__(256) fc_kernel(
    const float* __restrict__ fcw, const float* __restrict__ fcb)
{
    __shared__ float Wsm[NLAB * 768];
    __shared__ float Bsm[NLAB];

    int t = blockIdx.x;
    int tid = threadIdx.x;
    for (int i = tid; i < NLAB * 768; i += 256) Wsm[i] = fcw[i];
    if (tid < NLAB) Bsm[tid] = fcb[tid];
    __syncthreads();

    int b = tid & 63;
    int lg = tid >> 6;
    float acc[3];
#pragma unroll
    for (int q = 0; q < 3; q++) acc[q] = Bsm[lg * 3 + q];

    const float* hf = g_Hseq + ((size_t)0 * TT + t) * LHD * BB;
    const float* hb = g_Hseq + ((size_t)1 * TT + t) * LHD * BB;
    for (int j = 0; j < LHD; j++) {
        float vf = hf[j * BB + b];
        float vb = hb[j * BB + b];
#pragma unroll
        for (int q = 0; q < 3; q++) {
            int l = lg * 3 + q;
            acc[q] += vf * Wsm[l * 768 + j] + vb * Wsm[l * 768 + LHD + j];
        }
    }
#pragma unroll
    for (int q = 0; q < 3; q++)
        g_feats[((size_t)b * TT + t) * NLAB + lg * 3 + q] = acc[q];
}

// ---------------- kernel D: Viterbi ------------------------------------------
__global__ void __launch_bounds__(128) viterbi_kernel(
    const float* __restrict__ trans, const int* __restrict__ start_ptr,
    float* __restrict__ out)
{
    __shared__ float sf[TT * NLAB];
    __shared__ float ts[NLAB * NLAB];
    __shared__ float fv[NLAB];
    __shared__ unsigned char ptr[TT * NLAB];

    int b = blockIdx.x;
    int tid = threadIdx.x;
    for (int i = tid; i < TT * NLAB; i += 128) sf[i] = g_feats[(size_t)b * TT * NLAB + i];
    for (int i = tid; i < NLAB * NLAB; i += 128) ts[i] = trans[i];
    int start = *start_ptr;
    if (tid < NLAB) fv[tid] = (tid == start) ? 0.0f : NEGV;
    __syncthreads();

    if (tid < 32) {
        for (int t = 1; t < TT; t++) {
            float best = 0.0f; int arg = 0;
            if (tid < NLAB) {
                best = ts[tid * NLAB + 0] + fv[0]; arg = 0;
#pragma unroll
                for (int p = 1; p < NLAB; p++) {
                    float v = ts[tid * NLAB + p] + fv[p];
                    if (v > best) { best = v; arg = p; }
                }
                best += sf[t * NLAB + tid];
            }
            __syncwarp();
            if (tid < NLAB) {
                fv[tid] = best;
                ptr[t * NLAB + tid] = (unsigned char)arg;
            }
            __syncwarp();
        }
        if (tid == 0) {
            float bs = fv[0]; int last = 0;
            for (int l = 1; l < NLAB; l++)
                if (fv[l] > bs) { bs = fv[l]; last = l; }
            out[b] = bs;
            float* pp = out + 64 + (size_t)b * TT;
            int cur = last;
            pp[TT - 1] = (float)cur;
            for (int t = TT - 2; t >= 0; t--) {
                cur = ptr[(t + 1) * NLAB + cur];
                pp[t] = (float)cur;
            }
        }
    }
}

// ---------------- launch ------------------------------------------------------
extern "C" void kernel_launch(void* const* d_in, const int* in_sizes, int n_in,
                              void* d_out, int out_size)
{
    const float* hidden = (const float*)d_in[0];
    const float* h0     = (const float*)d_in[1];
    const float* c0     = (const float*)d_in[2];
    const float* w_ih_f = (const float*)d_in[3];
    const float* w_hh_f = (const float*)d_in[4];
    const float* b_ih_f = (const float*)d_in[5];
    const float* b_hh_f = (const float*)d_in[6];
    const float* w_ih_b = (const float*)d_in[7];
    const float* w_hh_b = (const float*)d_in[8];
    const float* b_ih_b = (const float*)d_in[9];
    const float* b_hh_b = (const float*)d_in[10];
    const float* fc_w   = (const float*)d_in[11];
    const float* fc_b   = (const float*)d_in[12];
    const float* transitions = (const float*)d_in[13];
    const int*   start_idx   = (const int*)d_in[14];

    static int attr_set = 0;
    int lstm_smem = (2 * A_ELEMS + 2 * B_ELEMS) * (int)sizeof(__nv_bfloat16);
    if (!attr_set) {
        cudaFuncSetAttribute(lstm_mma_kernel,
                             cudaFuncAttributeMaxDynamicSharedMemorySize,
                             lstm_smem);
        attr_set = 1;
    }

    split_w_kernel<<<dim3(1536, 2), 256>>>(w_ih_f, w_ih_b);
    split_h_kernel<<<dim3(512, 8), 256>>>(hidden);
    proj_mma_kernel<<<dim3(12, 2, 256), 256>>>(b_ih_f, b_hh_f,
                                                b_ih_b, b_hh_b);
    lstm_prep_kernel<<<128, 384>>>(h0);
    lstm_mma_kernel<<<NBLK_LSTM, 256, lstm_smem>>>(h0, c0, w_hh_f, w_hh_b);
    fc_kernel<<<512, 256>>>(fc_w, fc_b);
    viterbi_kernel<<<64, 128>>>(transitions, start_idx, (float*)d_out);
}

// round 14
// speedup vs baseline: 2.3101x; 1.4692x over previous
#include <cuda_runtime.h>
#include <cuda_bf16.h>
#include <cstdint>

// Problem constants
#define TT 512
#define BB 64
#define HH 768
#define LHD 384
#define G4 1536
#define NLAB 12
#define NEGV (-1000.0f)
#define NBLK_LSTM 96

// ---------------- scratch (static device memory; no allocation) -------------
// X[dir][t][col][b], col = gate*384 + j
__device__ float g_X[100663296];
// Hseq[dir][t][j][b]
__device__ float g_Hseq[25165824];
// feats[b][t][l]
__device__ float g_feats[64 * 512 * 12];
// per-CTA step-completion flags
__device__ volatile int g_flag[NBLK_LSTM];
// bf16 split of W_ih: [dir][split(hi/lo)][1536][768]
__device__ __align__(16) __nv_bfloat16 g_Wsp[2 * 2 * 1536 * 768];
// bf16 split of hidden: [t][split][b][768]
__device__ __align__(16) __nv_bfloat16 g_Hsp[512 * 2 * 64 * 768];
// double-buffered bf16 split of recurrent h: [buf][dir][split][b][384]
__device__ __align__(16) __nv_bfloat16 g_hrec[2 * 2 * 2 * 64 * 384];

__device__ __forceinline__ float sigm(float x) {
    return 1.0f / (1.0f + __expf(-x));
}

// warp-level bf16 tensor-core MMA (sm_80+ PTX, no 'a'-suffix features)
__device__ __forceinline__ void mma_bf16(
    float& c0, float& c1, float& c2, float& c3,
    uint32_t a0, uint32_t a1, uint32_t a2, uint32_t a3,
    uint32_t b0, uint32_t b1)
{
    asm volatile(
        "mma.sync.aligned.m16n8k16.row.col.f32.bf16.bf16.f32 "
        "{%0,%1,%2,%3}, {%4,%5,%6,%7}, {%8,%9}, {%0,%1,%2,%3};"
        : "+f"(c0), "+f"(c1), "+f"(c2), "+f"(c3)
        : "r"(a0), "r"(a1), "r"(a2), "r"(a3), "r"(b0), "r"(b1));
}

__device__ __forceinline__ uint32_t smem_u32(const void* p) {
    uint32_t a;
    asm("{ .reg .u64 t; cvta.to.shared.u64 t, %1; cvt.u32.u64 %0, t; }"
        : "=r"(a) : "l"(p));
    return a;
}

__device__ __forceinline__ void ldsm_x4(uint32_t* r, uint32_t addr) {
    asm volatile("ldmatrix.sync.aligned.m8n8.x4.shared.b16 {%0,%1,%2,%3}, [%4];"
        : "=r"(r[0]), "=r"(r[1]), "=r"(r[2]), "=r"(r[3]) : "r"(addr));
}
__device__ __forceinline__ void ldsm_x2(uint32_t* r, uint32_t addr) {
    asm volatile("ldmatrix.sync.aligned.m8n8.x2.shared.b16 {%0,%1}, [%2];"
        : "=r"(r[0]), "=r"(r[1]) : "r"(addr));
}

// ---------------- split W + prep (flags, h0 split) ---------------------------
__global__ void __launch_bounds__(256) split_w_kernel(
    const float* __restrict__ wf, const float* __restrict__ wb,
    const float* __restrict__ h0)
{
    int tid = threadIdx.x;
    if (blockIdx.x == G4) {
        // prep block: reset flags + split h0 into g_hrec buf 0
        int dir = blockIdx.y;
        if (dir == 0 && tid < NBLK_LSTM) g_flag[tid] = 0;
        __nv_bfloat16* dH = g_hrec + ((size_t)(dir * 2 + 0)) * BB * LHD;
        __nv_bfloat16* dL = g_hrec + ((size_t)(dir * 2 + 1)) * BB * LHD;
        const float* src = h0 + (size_t)dir * BB * LHD;
#pragma unroll
        for (int i = 0; i < 96; i++) {
            int idx = tid + i * 256;      // 0..24575
            float x = src[idx];
            __nv_bfloat16 hi = __float2bfloat16(x);
            __nv_bfloat16 lo = __float2bfloat16(x - __bfloat162float(hi));
            dH[idx] = hi;
            dL[idx] = lo;
        }
        return;
    }
    int col = blockIdx.x;
    int dir = blockIdx.y;
    const float* src = dir ? wb : wf;
#pragma unroll
    for (int i = 0; i < 3; i++) {
        int k = i * 256 + tid;
        float x = src[(size_t)col * HH + k];
        __nv_bfloat16 hi = __float2bfloat16(x);
        __nv_bfloat16 lo = __float2bfloat16(x - __bfloat162float(hi));
        g_Wsp[((size_t)(dir * 2 + 0) * G4 + col) * HH + k] = hi;
        g_Wsp[((size_t)(dir * 2 + 1) * G4 + col) * HH + k] = lo;
    }
}

__global__ void __launch_bounds__(256) split_h_kernel(
    const float* __restrict__ hid)
{
    int t = blockIdx.x;
    int b0 = blockIdx.y * 8;
    int tid = threadIdx.x;
    for (int bo = 0; bo < 8; bo++) {
        int b = b0 + bo;
#pragma unroll
        for (int i = 0; i < 3; i++) {
            int k = i * 256 + tid;
            float x = hid[((size_t)b * TT + t) * HH + k];
            __nv_bfloat16 hi = __float2bfloat16(x);
            __nv_bfloat16 lo = __float2bfloat16(x - __bfloat162float(hi));
            g_Hsp[((size_t)(t * 2 + 0) * BB + b) * HH + k] = hi;
            g_Hsp[((size_t)(t * 2 + 1) * BB + b) * HH + k] = lo;
        }
    }
}

// ---------------- kernel A: projection GEMM on mma.sync tensor cores --------
__global__ void __launch_bounds__(256) proj_mma_kernel(
    const float* __restrict__ bif, const float* __restrict__ bhf,
    const float* __restrict__ bib, const float* __restrict__ bhb)
{
    __shared__ __nv_bfloat16 Asm[128][40];
    __shared__ __nv_bfloat16 Bsm[128][40];

    int ct  = blockIdx.x;
    int dir = blockIdx.y;
    int tg  = blockIdx.z;
    int cb  = ct * 128;
    int t0  = tg * 2;

    int tid  = threadIdx.x;
    int lane = tid & 31;
    int warp = tid >> 5;
    int wm = (warp >> 2) * 64;
    int wn = (warp & 3) * 32;

    float acc[4][4][4];
#pragma unroll
    for (int mi = 0; mi < 4; mi++)
#pragma unroll
        for (int ni = 0; ni < 4; ni++)
#pragma unroll
            for (int q = 0; q < 4; q++) acc[mi][ni][q] = 0.0f;

    const float* b1 = dir ? bib : bif;
    const float* b2 = dir ? bhb : bhf;
    float bias0[4], bias1[4];
#pragma unroll
    for (int mi = 0; mi < 4; mi++) {
        int m0 = wm + mi * 16 + (lane >> 2);
        bias0[mi] = b1[cb + m0] + b2[cb + m0];
        bias1[mi] = b1[cb + m0 + 8] + b2[cb + m0 + 8];
    }

    int r = tid >> 1;
    int seg = tid & 1;
    int tlL = r >> 6;
    int bbL = r & 63;

    for (int term = 0; term < 3; term++) {
        int spA = (term == 2) ? 1 : 0;
        int spB = (term == 1) ? 1 : 0;
        const __nv_bfloat16* Abase = g_Wsp +
            ((size_t)(dir * 2 + spA) * G4 + cb + r) * HH + seg * 16;
        const __nv_bfloat16* Bbase = g_Hsp +
            ((size_t)((t0 + tlL) * 2 + spB) * BB + bbL) * HH + seg * 16;

        for (int kc = 0; kc < 24; kc++) {
            uint4 av0 = *(const uint4*)(Abase + kc * 32);
            uint4 av1 = *(const uint4*)(Abase + kc * 32 + 8);
            uint4 bv0 = *(const uint4*)(Bbase + kc * 32);
            uint4 bv1 = *(const uint4*)(Bbase + kc * 32 + 8);
            __syncthreads();
            *(uint4*)&Asm[r][seg * 16]     = av0;
            *(uint4*)&Asm[r][seg * 16 + 8] = av1;
            *(uint4*)&Bsm[r][seg * 16]     = bv0;
            *(uint4*)&Bsm[r][seg * 16 + 8] = bv1;
            __syncthreads();

#pragma unroll
            for (int ks = 0; ks < 2; ks++) {
                int gk = ks * 16 + (lane & 3) * 2;
                uint32_t ar[4][4];
#pragma unroll
                for (int mi = 0; mi < 4; mi++) {
                    int gm = wm + mi * 16 + (lane >> 2);
                    ar[mi][0] = *(const uint32_t*)&Asm[gm][gk];
                    ar[mi][1] = *(const uint32_t*)&Asm[gm + 8][gk];
                    ar[mi][2] = *(const uint32_t*)&Asm[gm][gk + 8];
                    ar[mi][3] = *(const uint32_t*)&Asm[gm + 8][gk + 8];
                }
#pragma unroll
                for (int ni = 0; ni < 4; ni++) {
                    int gn = wn + ni * 8 + (lane >> 2);
                    uint32_t br0 = *(const uint32_t*)&Bsm[gn][gk];
                    uint32_t br1 = *(const uint32_t*)&Bsm[gn][gk + 8];
#pragma unroll
                    for (int mi = 0; mi < 4; mi++)
                        mma_bf16(acc[mi][ni][0], acc[mi][ni][1],
                                 acc[mi][ni][2], acc[mi][ni][3],
                                 ar[mi][0], ar[mi][1], ar[mi][2], ar[mi][3],
                                 br0, br1);
                }
            }
        }
    }

#pragma unroll
    for (int mi = 0; mi < 4; mi++) {
#pragma unroll
        for (int ni = 0; ni < 4; ni++) {
            int m0 = wm + mi * 16 + (lane >> 2);
            int n = wn + ni * 8 + (lane & 3) * 2;
            int tl = n >> 6;
            int bb = n & 63;
            float* op = g_X +
                (((size_t)dir * TT + t0 + tl) * G4 + cb) * BB;
            float2 v0, v1;
            v0.x = acc[mi][ni][0] + bias0[mi];
            v0.y = acc[mi][ni][1] + bias0[mi];
            v1.x = acc[mi][ni][2] + bias1[mi];
            v1.y = acc[mi][ni][3] + bias1[mi];
            *(float2*)&op[(size_t)m0 * BB + bb] = v0;
            *(float2*)&op[(size_t)(m0 + 8) * BB + bb] = v1;
        }
    }
}

// ---------------- kernel B: persistent BiLSTM recurrence (tensor cores) -----
// 96 CTAs: (dir, 32 gate-cols) x 64 batch. Warp tile M=32 x N=8, K=384, 3 terms.
// ldmatrix fragment loads; coalesced staged epilogue.
#define LPAD 392
#define A_ELEMS (32 * LPAD)
#define B_ELEMS (64 * LPAD)
#define STG_PAD 68
#define LSTM_SMEM ((2 * A_ELEMS + 2 * B_ELEMS) * 2 + 8 * STG_PAD * 4)

__global__ void __launch_bounds__(256) lstm_mma_kernel(
    const float* __restrict__ c0,
    const float* __restrict__ whf, const float* __restrict__ whb)
{
    extern __shared__ __nv_bfloat16 smb[];
    __nv_bfloat16* AsmH = smb;
    __nv_bfloat16* AsmL = smb + A_ELEMS;
    __nv_bfloat16* BsmH = smb + 2 * A_ELEMS;
    __nv_bfloat16* BsmL = smb + 2 * A_ELEMS + B_ELEMS;
    float* stage = (float*)(smb + 2 * A_ELEMS + 2 * B_ELEMS);

    int tile = blockIdx.x;
    int dir = tile / 48;
    int ug = tile % 48;                    // units [ug*8, ug*8+8)
    const float* W = dir ? whb : whf;

    int tid  = threadIdx.x;
    int lane = tid & 31;
    int warp = tid >> 5;

    // ---- one-time W slice preload + bf16 split
    // A row m = gate*8+u  <->  W row gate*384 + ug*8 + u
    {
        int m = tid >> 3;                  // 0..31
        int kseg = (tid & 7) * 48;
        int wrow = (m >> 3) * LHD + ug * 8 + (m & 7);
        const float* src = W + (size_t)wrow * LHD + kseg;
#pragma unroll
        for (int i = 0; i < 48; i++) {
            float x = src[i];
            __nv_bfloat16 hi = __float2bfloat16(x);
            __nv_bfloat16 lo = __float2bfloat16(x - __bfloat162float(hi));
            AsmH[m * LPAD + kseg + i] = hi;
            AsmL[m * LPAD + kseg + i] = lo;
        }
    }

    // thread ownership: unit j = ug*8 + uloc, batches b0, b0+1
    int uloc = lane >> 2;
    int j = ug * 8 + uloc;
    int b0 = warp * 8 + (lane & 3) * 2;

    float cr0 = c0[((size_t)(dir * BB + b0)) * LHD + j];
    float cr1 = c0[((size_t)(dir * BB + b0 + 1)) * LHD + j];

    // ---- ldmatrix lane addresses (byte offsets advance by kc*32)
    uint32_t sb = smem_u32(smb);
    int a_r = (lane & 7) + ((lane >> 3) & 1) * 8;   // 0..15
    int a_c = (lane >> 4) * 8;                       // 0 or 8
    uint32_t aH_m0 = sb + (uint32_t)((a_r) * LPAD + a_c) * 2;
    uint32_t aH_m1 = aH_m0 + 16 * LPAD * 2;
    uint32_t aL_m0 = aH_m0 + A_ELEMS * 2;
    uint32_t aL_m1 = aH_m1 + A_ELEMS * 2;
    int b_r = lane & 7;
    int b_c = ((lane >> 3) & 1) * 8;
    uint32_t bH_ad = sb + 2 * A_ELEMS * 2 +
                     (uint32_t)((warp * 8 + b_r) * LPAD + b_c) * 2;
    uint32_t bL_ad = bH_ad + B_ELEMS * 2;

    for (int s = 0; s < TT; s++) {
        int t = dir ? (TT - 1 - s) : s;

        // ---- prefetch x gate values (before the wait)
        float2 xv[4];
        {
            const float* xb = g_X + ((size_t)(dir * TT + t)) * G4 * BB;
#pragma unroll
            for (int g = 0; g < 4; g++)
                xv[g] = *(const float2*)&xb[((size_t)g * LHD + j) * BB + b0];
        }

        // ---- wait for previous step of this direction
        if (s > 0) {
            if (tid < 48) {
                while (g_flag[dir * 48 + tid] < s) { }
            }
        }
        __syncthreads();
        if (s > 0) __threadfence();

        // ---- load B = h split [64][384] hi+lo from g_hrec buf (s&1)
        {
            int rb = s & 1;
            const __nv_bfloat16* srcH = g_hrec +
                ((size_t)((rb * 2 + dir) * 2 + 0)) * BB * LHD;
            const __nv_bfloat16* srcL = g_hrec +
                ((size_t)((rb * 2 + dir) * 2 + 1)) * BB * LHD;
#pragma unroll
            for (int i = 0; i < 12; i++) {
                int u = tid + i * 256;
                int row = u / 48;
                int c16 = u % 48;
                uint4 v = *(const uint4*)(srcH + (size_t)row * LHD + c16 * 8);
                *(uint4*)&BsmH[row * LPAD + c16 * 8] = v;
            }
#pragma unroll
            for (int i = 0; i < 12; i++) {
                int u = tid + i * 256;
                int row = u / 48;
                int c16 = u % 48;
                uint4 v = *(const uint4*)(srcL + (size_t)row * LHD + c16 * 8);
                *(uint4*)&BsmL[row * LPAD + c16 * 8] = v;
            }
        }
        __syncthreads();

        // ---- MMA via ldmatrix: 3 split terms, K=384
        float acc0[4] = {0.f, 0.f, 0.f, 0.f};
        float acc1[4] = {0.f, 0.f, 0.f, 0.f};

#pragma unroll 6
        for (int kc = 0; kc < 24; kc++) {
            uint32_t ko = (uint32_t)kc * 32;
            uint32_t aH0[4], aH1[4], aL0[4], aL1[4], bH[2], bL[2];
            ldsm_x4(aH0, aH_m0 + ko);
            ldsm_x4(aH1, aH_m1 + ko);
            ldsm_x2(bH, bH_ad + ko);
            ldsm_x2(bL, bL_ad + ko);
            ldsm_x4(aL0, aL_m0 + ko);
            ldsm_x4(aL1, aL_m1 + ko);
            mma_bf16(acc0[0], acc0[1], acc0[2], acc0[3],
                     aH0[0], aH0[1], aH0[2], aH0[3], bH[0], bH[1]);
            mma_bf16(acc1[0], acc1[1], acc1[2], acc1[3],
                     aH1[0], aH1[1], aH1[2], aH1[3], bH[0], bH[1]);
            mma_bf16(acc0[0], acc0[1], acc0[2], acc0[3],
                     aH0[0], aH0[1], aH0[2], aH0[3], bL[0], bL[1]);
            mma_bf16(acc1[0], acc1[1], acc1[2], acc1[3],
                     aH1[0], aH1[1], aH1[2], aH1[3], bL[0], bL[1]);
            mma_bf16(acc0[0], acc0[1], acc0[2], acc0[3],
                     aL0[0], aL0[1], aL0[2], aL0[3], bH[0], bH[1]);
            mma_bf16(acc1[0], acc1[1], acc1[2], acc1[3],
                     aL1[0], aL1[1], aL1[2], aL1[3], bH[0], bH[1]);
        }

        // ---- gate nonlinearities (acc0: c0/c1 gate i, c2/c3 gate f;
        //                            acc1: c0/c1 gate g, c2/c3 gate o)
        float h0v, h1v;
        {
            float gi = acc0[0] + xv[0].x;
            float gf = acc0[2] + xv[1].x;
            float gg = acc1[0] + xv[2].x;
            float go = acc1[2] + xv[3].x;
            cr0 = sigm(gf) * cr0 + sigm(gi) * tanhf(gg);
            h0v = sigm(go) * tanhf(cr0);
        }
        {
            float gi = acc0[1] + xv[0].y;
            float gf = acc0[3] + xv[1].y;
            float gg = acc1[1] + xv[2].y;
            float go = acc1[3] + xv[3].y;
            cr1 = sigm(gf) * cr1 + sigm(gi) * tanhf(gg);
            h1v = sigm(go) * tanhf(cr1);
        }

        // ---- stage h in smem, then coalesced writeout
        stage[uloc * STG_PAD + b0]     = h0v;
        stage[uloc * STG_PAD + b0 + 1] = h1v;
        __syncthreads();

        {
            // g_Hseq [j][b] fp32, float2 per thread
            int v = tid * 2;
            int jl = v >> 6;
            int bb = v & 63;
            float2 hv = make_float2(stage[jl * STG_PAD + bb],
                                    stage[jl * STG_PAD + bb + 1]);
            *(float2*)&g_Hseq[(((size_t)dir * TT + t) * LHD + ug * 8 + jl) * BB + bb] = hv;

            // g_hrec [b][384] bf16 hi/lo, bf16x2 per thread
            int wbuf = (s + 1) & 1;
            __nv_bfloat16* dstH = g_hrec +
                ((size_t)((wbuf * 2 + dir) * 2 + 0)) * BB * LHD;
            __nv_bfloat16* dstL = g_hrec +
                ((size_t)((wbuf * 2 + dir) * 2 + 1)) * BB * LHD;
            int bb2 = tid >> 2;
            int pr  = (tid & 3) * 2;
            float v0 = stage[pr * STG_PAD + bb2];
            float v1 = stage[(pr + 1) * STG_PAD + bb2];
            __nv_bfloat16 h0b = __float2bfloat16(v0);
            __nv_bfloat16 h1b = __float2bfloat16(v1);
            __nv_bfloat16 l0b = __float2bfloat16(v0 - __bfloat162float(h0b));
            __nv_bfloat16 l1b = __float2bfloat16(v1 - __bfloat162float(h1b));
            uint32_t packH = ((uint32_t)*(uint16_t*)&h0b) |
                             ((uint32_t)*(uint16_t*)&h1b << 16);
            uint32_t packL = ((uint32_t)*(uint16_t*)&l0b) |
                             ((uint32_t)*(uint16_t*)&l1b << 16);
            *(uint32_t*)&dstH[(size_t)bb2 * LHD + ug * 8 + pr] = packH;
            *(uint32_t*)&dstL[(size_t)bb2 * LHD + ug * 8 + pr] = packL;
        }

        // ---- release
        __threadfence();
        __syncthreads();
        if (tid == 0) g_flag[tile] = s + 1;
    }
}

// ---------------- kernel C: FC emissions -------------------------------------
__global__ void __launch_bounds__(256) fc_kernel(
    const float* __restrict__ fcw, const float* __restrict__ fcb)
{
    __shared__ float Wsm[NLAB * 768];
    __shared__ float Bsm[NLAB];

    int t = blockIdx.x;
    int tid = threadIdx.x;
    for (int i = tid; i < NLAB * 768; i += 256) Wsm[i] = fcw[i];
    if (tid < NLAB) Bsm[tid] = fcb[tid];
    __syncthreads();

    int b = tid & 63;
    int lg = tid >> 6;
    float acc[3];
#pragma unroll
    for (int q = 0; q < 3; q++) acc[q] = Bsm[lg * 3 + q];

    const float* hf = g_Hseq + ((size_t)0 * TT + t) * LHD * BB;
    const float* hb = g_Hseq + ((size_t)1 * TT + t) * LHD * BB;
    for (int j = 0; j < LHD; j++) {
        float vf = hf[j * BB + b];
        float vb = hb[j * BB + b];
#pragma unroll
        for (int q = 0; q < 3; q++) {
            int l = lg * 3 + q;
            acc[q] += vf * Wsm[l * 768 + j] + vb * Wsm[l * 768 + LHD + j];
        }
    }
#pragma unroll
    for (int q = 0; q < 3; q++)
        g_feats[((size_t)b * TT + t) * NLAB + lg * 3 + q] = acc[q];
}

// ---------------- kernel D: Viterbi ------------------------------------------
__global__ void __launch_bounds__(128) viterbi_kernel(
    const float* __restrict__ trans, const int* __restrict__ start_ptr,
    float* __restrict__ out)
{
    __shared__ float sf[TT * NLAB];
    __shared__ float ts[NLAB * NLAB];
    __shared__ float fv[NLAB];
    __shared__ unsigned char ptr[TT * NLAB];

    int b = blockIdx.x;
    int tid = threadIdx.x;
    for (int i = tid; i < TT * NLAB; i += 128) sf[i] = g_feats[(size_t)b * TT * NLAB + i];
    for (int i = tid; i < NLAB * NLAB; i += 128) ts[i] = trans[i];
    int start = *start_ptr;
    if (tid < NLAB) fv[tid] = (tid == start) ? 0.0f : NEGV;
    __syncthreads();

    if (tid < 32) {
        for (int t = 1; t < TT; t++) {
            float best = 0.0f; int arg = 0;
            if (tid < NLAB) {
                best = ts[tid * NLAB + 0] + fv[0]; arg = 0;
#pragma unroll
                for (int p = 1; p < NLAB; p++) {
                    float v = ts[tid * NLAB + p] + fv[p];
                    if (v > best) { best = v; arg = p; }
                }
                best += sf[t * NLAB + tid];
            }
            __syncwarp();
            if (tid < NLAB) {
                fv[tid] = best;
                ptr[t * NLAB + tid] = (unsigned char)arg;
            }
            __syncwarp();
        }
        if (tid == 0) {
            float bs = fv[0]; int last = 0;
            for (int l = 1; l < NLAB; l++)
                if (fv[l] > bs) { bs = fv[l]; last = l; }
            out[b] = bs;
            float* pp = out + 64 + (size_t)b * TT;
            int cur = last;
            pp[TT - 1] = (float)cur;
            for (int t = TT - 2; t >= 0; t--) {
                cur = ptr[(t + 1) * NLAB + cur];
                pp[t] = (float)cur;
            }
        }
    }
}

// ---------------- launch ------------------------------------------------------
extern "C" void kernel_launch(void* const* d_in, const int* in_sizes, int n_in,
                              void* d_out, int out_size)
{
    const float* hidden = (const float*)d_in[0];
    const float* h0     = (const float*)d_in[1];
    const float* c0     = (const float*)d_in[2];
    const float* w_ih_f = (const float*)d_in[3];
    const float* w_hh_f = (const float*)d_in[4];
    const float* b_ih_f = (const float*)d_in[5];
    const float* b_hh_f = (const float*)d_in[6];
    const float* w_ih_b = (const float*)d_in[7];
    const float* w_hh_b = (const float*)d_in[8];
    const float* b_ih_b = (const float*)d_in[9];
    const float* b_hh_b = (const float*)d_in[10];
    const float* fc_w   = (const float*)d_in[11];
    const float* fc_b   = (const float*)d_in[12];
    const float* transitions = (const float*)d_in[13];
    const int*   start_idx   = (const int*)d_in[14];

    static int attr_set = 0;
    if (!attr_set) {
        cudaFuncSetAttribute(lstm_mma_kernel,
                             cudaFuncAttributeMaxDynamicSharedMemorySize,
                             LSTM_SMEM);
        attr_set = 1;
    }

    split_w_kernel<<<dim3(G4 + 1, 2), 256>>>(w_ih_f, w_ih_b, h0);
    split_h_kernel<<<dim3(512, 8), 256>>>(hidden);
    proj_mma_kernel<<<dim3(12, 2, 256), 256>>>(b_ih_f, b_hh_f,
                                                b_ih_b, b_hh_b);
    lstm_mma_kernel<<<NBLK_LSTM, 256, LSTM_SMEM>>>(c0, w_hh_f, w_hh_b);
    fc_kernel<<<512, 256>>>(fc_w, fc_b);
    viterbi_kernel<<<64, 128>>>(transitions, start_idx, (float*)d_out);
}